// round 1
// baseline (speedup 1.0000x reference)
#include <cuda_runtime.h>
#include <math.h>

#define NLV  4
#define CPL  1024
#define NC   4096
#define IND  512
#define HID  1024
#define OUTD 512
#define MLPD 128
#define G3   3072
#define MEMK 513   // OUT + tension col

// ---------------- scratch (device globals; no allocations allowed) ----------------
__device__ float g_xa[2 * NLV * MLPD];        // folded x-part bias for ea/eg MLP1
__device__ float g_za[NC * MLPD];
__device__ float g_zg[NC * MLPD];
__device__ float g_out[NC * MEMK];            // [out(512) | tension(1)] per cell
__device__ float g_gi[NC * G3];
__device__ float g_gh[NC * G3];
__device__ float g_newh[NC * HID];
__device__ float g_lm[NLV * HID];             // level means (pre-delta)
__device__ float g_pz[3 * HID];
__device__ float g_pred[3 * HID];
__device__ float g_delta[NLV * HID];
__device__ float g_mdelta[NLV * HID];
__device__ float g_gop[HID];

// ---------------- generic batched SGEMM ----------------
// C[z] = act( alpha * A[z] @ op(B[z]) + beta * C[z] + bscale * bias[z][n] )
// BT=false: B is [K x N]; BT=true: B is [N x K] (we multiply by B^T).
// M, N are multiples of 64 (grid covers exactly); K arbitrary (zero-fill guard).
template<bool BT>
__global__ void __launch_bounds__(256)
gemm_k(const float* __restrict__ A, int lda, long sA,
       const float* __restrict__ B, int ldb, long sB,
       float* __restrict__ C, int ldc, long sC,
       int K,
       const float* __restrict__ bias, int sBias, float bscale,
       float alpha, float beta, int act)
{
    __shared__ __align__(16) float As[16][68];
    __shared__ __align__(16) float Bs[16][68];
    const int bz = blockIdx.z;
    A += bz * sA; B += bz * sB; C += bz * sC;
    const float* bp = bias ? bias + (long)bz * sBias : nullptr;
    const int m0 = blockIdx.y << 6, n0 = blockIdx.x << 6;
    const int tid = threadIdx.x;
    const int tx = tid & 15, ty = tid >> 4;
    float acc[4][4] = {};
    for (int k0 = 0; k0 < K; k0 += 16) {
#pragma unroll
        for (int i = 0; i < 4; i++) {
            int e = tid + (i << 8);
            int m = e >> 4, k = e & 15;
            As[k][m] = (k0 + k < K) ? A[(size_t)(m0 + m) * lda + k0 + k] : 0.f;
        }
#pragma unroll
        for (int i = 0; i < 4; i++) {
            int e = tid + (i << 8);
            if (!BT) {
                int k = e >> 6, n = e & 63;
                Bs[k][n] = (k0 + k < K) ? B[(size_t)(k0 + k) * ldb + n0 + n] : 0.f;
            } else {
                int n = e >> 4, k = e & 15;
                Bs[k][n] = (k0 + k < K) ? B[(size_t)(n0 + n) * ldb + k0 + k] : 0.f;
            }
        }
        __syncthreads();
#pragma unroll
        for (int kk = 0; kk < 16; kk++) {
            float4 av = *reinterpret_cast<const float4*>(&As[kk][ty << 2]);
            float4 bv = *reinterpret_cast<const float4*>(&Bs[kk][tx << 2]);
            float a[4] = {av.x, av.y, av.z, av.w};
            float b[4] = {bv.x, bv.y, bv.z, bv.w};
#pragma unroll
            for (int i2 = 0; i2 < 4; i2++)
#pragma unroll
                for (int j2 = 0; j2 < 4; j2++)
                    acc[i2][j2] = fmaf(a[i2], b[j2], acc[i2][j2]);
        }
        __syncthreads();
    }
#pragma unroll
    for (int i2 = 0; i2 < 4; i2++) {
        int m = m0 + (ty << 2) + i2;
#pragma unroll
        for (int j2 = 0; j2 < 4; j2++) {
            int n = n0 + (tx << 2) + j2;
            float v = alpha * acc[i2][j2];
            if (beta != 0.f) v = fmaf(beta, C[(size_t)m * ldc + n], v);
            if (bp)          v = fmaf(bscale, bp[n], v);
            if (act)         v = fmaxf(v, 0.f);
            C[(size_t)m * ldc + n] = v;
        }
    }
}

// x is identical for every cell: fold x @ W1[:512] + b1 into a per-level bias.
__global__ void xa_kernel(const float* __restrict__ x,
                          const float* __restrict__ eaW1, const float* __restrict__ eab1,
                          const float* __restrict__ egW1, const float* __restrict__ egb1)
{
    int which = blockIdx.x, l = blockIdx.y, m = threadIdx.x; // 128 threads
    const float* W = (which ? egW1 : eaW1) + (size_t)l * (IND + HID) * MLPD;
    const float* b = (which ? egb1 : eab1) + l * MLPD;
    float acc = b[m];
    for (int i = 0; i < IND; i++) acc = fmaf(x[i], W[(size_t)i * MLPD + m], acc);
    g_xa[which * (NLV * MLPD) + l * MLPD + m] = acc;
}

// per-cell tension = mean(out^2) written into column 512 of g_out
__global__ void tension_kernel()
{
    int c = blockIdx.x, t = threadIdx.x; // 128 threads
    const float* row = g_out + (size_t)c * MEMK;
    float s = 0.f;
#pragma unroll
    for (int q = 0; q < 4; q++) { float v = row[t + 128 * q]; s = fmaf(v, v, s); }
    __shared__ float sm[128];
    sm[t] = s; __syncthreads();
    for (int o = 64; o > 0; o >>= 1) { if (t < o) sm[t] += sm[t + o]; __syncthreads(); }
    if (t == 0) g_out[(size_t)c * MEMK + OUTD] = sm[0] * (1.f / OUTD);
}

__global__ void gate_kernel(const float* __restrict__ hid)
{
    int idx = blockIdx.x * blockDim.x + threadIdx.x; // NC*HID
    int c = idx >> 10, j = idx & 1023;
    size_t base = (size_t)c * G3;
    float ir = g_gi[base + j], iz = g_gi[base + HID + j], inn = g_gi[base + 2 * HID + j];
    float hr = g_gh[base + j], hz = g_gh[base + HID + j], hn  = g_gh[base + 2 * HID + j];
    float r = 1.f / (1.f + expf(-(ir + hr)));
    float z = 1.f / (1.f + expf(-(iz + hz)));
    float n = tanhf(inn + r * hn);
    float h = hid[idx];
    g_newh[idx] = (1.f - z) * n + z * h;
}

__global__ void colsum_kernel()
{
    int l = blockIdx.y, j = blockIdx.x * 128 + threadIdx.x;
    const float* p = g_newh + ((size_t)l * CPL) * HID + j;
    float s = 0.f;
    for (int c = 0; c < CPL; c++) s += p[(size_t)c * HID];
    g_lm[l * HID + j] = s * (1.f / CPL);
}

__global__ void pred1_kernel(const float* __restrict__ W1, const float* __restrict__ b1)
{
    int l = blockIdx.x, t = threadIdx.x; // 3 blocks x 256
    float acc[4];
#pragma unroll
    for (int q = 0; q < 4; q++) acc[q] = b1[l * HID + t + 256 * q];
    const float* lm = g_lm + (l + 1) * HID;
    const float* W  = W1 + (size_t)l * HID * HID;
    for (int i = 0; i < HID; i++) {
        float a = lm[i];
#pragma unroll
        for (int q = 0; q < 4; q++) acc[q] = fmaf(a, W[(size_t)i * HID + t + 256 * q], acc[q]);
    }
#pragma unroll
    for (int q = 0; q < 4; q++) g_pz[l * HID + t + 256 * q] = fmaxf(acc[q], 0.f);
}

__global__ void pred2_kernel(const float* __restrict__ W2, const float* __restrict__ b2)
{
    int l = blockIdx.x, t = threadIdx.x;
    float acc[4];
#pragma unroll
    for (int q = 0; q < 4; q++) acc[q] = b2[l * HID + t + 256 * q];
    const float* pz = g_pz + l * HID;
    const float* W  = W2 + (size_t)l * HID * HID;
    for (int i = 0; i < HID; i++) {
        float a = pz[i];
#pragma unroll
        for (int q = 0; q < 4; q++) acc[q] = fmaf(a, W[(size_t)i * HID + t + 256 * q], acc[q]);
    }
#pragma unroll
    for (int q = 0; q < 4; q++) g_pred[l * HID + t + 256 * q] = acc[q];
}

__global__ void finalize_kernel()
{
    int j = threadIdx.x; // 1024
    float lm0 = g_lm[j], lm1 = g_lm[HID + j], lm2 = g_lm[2 * HID + j], lm3 = g_lm[3 * HID + j];
    float pe0 = (g_pred[j] - lm0) * 0.05f;
    float pe1 = (g_pred[HID + j] - lm1) * 0.05f;
    float pe2 = (g_pred[2 * HID + j] - lm2) * 0.05f;
    float d0 = pe0;
    float d1 = pe1 - 0.5f * pe0;
    float d2 = pe2 - 0.5f * pe1;
    float d3 = -0.5f * pe2;
    g_delta[j] = d0; g_delta[HID + j] = d1; g_delta[2 * HID + j] = d2; g_delta[3 * HID + j] = d3;
    float m0 = lm0 + d0, m1 = lm1 + d1, m2 = lm2 + d2, m3 = lm3 + d3;
    g_mdelta[j] = m0; g_mdelta[HID + j] = m1; g_mdelta[2 * HID + j] = m2; g_mdelta[3 * HID + j] = m3;
    g_gop[j] = (m0 + m1 + m2 + m3) * 0.25f;
}

// hh = 0.85^2*(new_h+delta) + (1-0.85^2)*(lm+delta); debate blend on first C/4 cells.
__global__ void hh_kernel(float* __restrict__ out, const int* __restrict__ stepp)
{
    int idx = blockIdx.x * blockDim.x + threadIdx.x;
    int c = idx >> 10, j = idx & 1023;
    int l = c >> 10, cl = c & 1023;
    float d = g_delta[l * HID + j];
    float v = 0.7225f * (g_newh[idx] + d) + 0.2775f * g_mdelta[l * HID + j];
    if (*stepp > 5 && cl < (CPL / 4)) v = 0.85f * v + 0.15f * g_gop[j];
    out[513 + idx] = v;
}

__global__ void combined_kernel(const float* __restrict__ W, const float* __restrict__ b,
                                float* __restrict__ out)
{
    int n = blockIdx.x * blockDim.x + threadIdx.x; // 512
    float acc = b[n];
    for (int i = 0; i < NLV * HID; i++) acc = fmaf(g_lm[i], W[(size_t)i * OUTD + n], acc);
    out[n] = acc;
}

__global__ void avgten_kernel(float* __restrict__ out)
{
    __shared__ float sm[1024];
    int t = threadIdx.x;
    float s = 0.f;
#pragma unroll
    for (int q = 0; q < 4; q++) s += g_out[(size_t)(t + 1024 * q) * MEMK + OUTD];
    sm[t] = s; __syncthreads();
    for (int o = 512; o > 0; o >>= 1) { if (t < o) sm[t] += sm[t + o]; __syncthreads(); }
    if (t == 0) out[OUTD] = sm[0] * (1.f / NC);
}

static float* sym(const void* s)
{
    void* p = nullptr;
    cudaGetSymbolAddress(&p, s);
    return (float*)p;
}

extern "C" void kernel_launch(void* const* d_in, const int* in_sizes, int n_in,
                              void* d_out, int out_size)
{
    const float* x     = (const float*)d_in[0];
    const float* hid   = (const float*)d_in[1];
    const float* eaW1  = (const float*)d_in[2];
    const float* eab1  = (const float*)d_in[3];
    const float* eaW2  = (const float*)d_in[4];
    const float* eab2  = (const float*)d_in[5];
    const float* egW1  = (const float*)d_in[6];
    const float* egb1  = (const float*)d_in[7];
    const float* egW2  = (const float*)d_in[8];
    const float* egb2  = (const float*)d_in[9];
    const float* Wih   = (const float*)d_in[10];
    const float* Whh   = (const float*)d_in[11];
    const float* bih   = (const float*)d_in[12];
    const float* bhh   = (const float*)d_in[13];
    const float* pW1   = (const float*)d_in[14];
    const float* pb1   = (const float*)d_in[15];
    const float* pW2   = (const float*)d_in[16];
    const float* pb2   = (const float*)d_in[17];
    const float* peiW  = (const float*)d_in[18];
    const float* peib  = (const float*)d_in[19];
    const int*   stepp = (const int*)d_in[20];
    float* out = (float*)d_out;

    float* za   = sym(g_za);
    float* zg   = sym(g_zg);
    float* outb = sym(g_out);
    float* gi   = sym(g_gi);
    float* gh   = sym(g_gh);
    float* xa   = sym(g_xa);

    // 1) fold x into MLP1 bias
    xa_kernel<<<dim3(2, NLV), 128>>>(x, eaW1, eab1, egW1, egb1);

    // 2) za = relu(h @ W1[512:] + xa_ea) ; zg likewise
    gemm_k<false><<<dim3(MLPD / 64, CPL / 64, NLV), 256>>>(
        hid, HID, (long)CPL * HID,
        eaW1 + (size_t)IND * MLPD, MLPD, (long)(IND + HID) * MLPD,
        za, MLPD, (long)CPL * MLPD, HID,
        xa, MLPD, 1.f, 1.f, 0.f, 1);
    gemm_k<false><<<dim3(MLPD / 64, CPL / 64, NLV), 256>>>(
        hid, HID, (long)CPL * HID,
        egW1 + (size_t)IND * MLPD, MLPD, (long)(IND + HID) * MLPD,
        zg, MLPD, (long)CPL * MLPD, HID,
        xa + NLV * MLPD, MLPD, 1.f, 1.f, 0.f, 1);

    // 3) out = (za@W2a + b2a) - (zg@W2g + b2g)   -> g_out cols [0,512)
    gemm_k<false><<<dim3(OUTD / 64, CPL / 64, NLV), 256>>>(
        za, MLPD, (long)CPL * MLPD,
        eaW2, OUTD, (long)MLPD * OUTD,
        outb, MEMK, (long)CPL * MEMK, MLPD,
        eab2, OUTD, 1.f, 1.f, 0.f, 0);
    gemm_k<false><<<dim3(OUTD / 64, CPL / 64, NLV), 256>>>(
        zg, MLPD, (long)CPL * MLPD,
        egW2, OUTD, (long)MLPD * OUTD,
        outb, MEMK, (long)CPL * MEMK, MLPD,
        egb2, OUTD, -1.f, -1.f, 1.f, 0);

    // 4) tension -> g_out col 512 (mem_in = g_out row, K=513)
    tension_kernel<<<NC, 128>>>();

    // 5) GRU gi / gh (B transposed: weights are [3072 x K])
    gemm_k<true><<<dim3(G3 / 64, CPL / 64, NLV), 256>>>(
        outb, MEMK, (long)CPL * MEMK,
        Wih, MEMK, (long)G3 * MEMK,
        gi, G3, (long)CPL * G3, MEMK,
        bih, G3, 1.f, 1.f, 0.f, 0);
    gemm_k<true><<<dim3(G3 / 64, CPL / 64, NLV), 256>>>(
        hid, HID, (long)CPL * HID,
        Whh, HID, (long)G3 * HID,
        gh, G3, (long)CPL * G3, HID,
        bhh, G3, 1.f, 1.f, 0.f, 0);

    // 6) gates -> new_h
    gate_kernel<<<(NC * HID) / 256, 256>>>(hid);

    // 7) level means
    colsum_kernel<<<dim3(HID / 128, NLV), 128>>>();

    // 8) top-down predictors + deltas
    pred1_kernel<<<3, 256>>>(pW1, pb1);
    pred2_kernel<<<3, 256>>>(pW2, pb2);
    finalize_kernel<<<1, 1024>>>();

    // 9) hh output (with debate blend)
    hh_kernel<<<(NC * HID) / 256, 256>>>(out, stepp);

    // 10) combined head + avg tension
    combined_kernel<<<OUTD / 256, 256>>>(peiW, peib, out);
    avgten_kernel<<<1, 1024>>>(out);
}

// round 4
// speedup vs baseline: 1.4334x; 1.4334x over previous
#include <cuda_runtime.h>
#include <cuda_bf16.h>
#include <cstdint>
#include <math.h>

#define NLV  4
#define CPL  1024
#define NC   4096
#define IND  512
#define HID  1024
#define OUTD 512
#define MLPD 128
#define G3   3072
#define MEMK 513

// K2 (tripled-K) sizes
#define K2_H   3072   // K=1024 -> 3*1024
#define KP_M   576    // 513 padded to 576
#define K2_M   1728   // 3*576
#define K2_Z   768    // 3*256 (za|zg concat K=256)

// ---------------- scratch (device globals) ----------------
__device__ float g_xa2[NLV * 256];
__device__ float g_zab[NC * 256];
__device__ float g_out[NC * MEMK];
__device__ float g_gi[(size_t)NC * G3];
__device__ float g_gh[(size_t)NC * G3];
__device__ float g_newh[NC * HID];
__device__ float g_lm[NLV * HID];
__device__ float g_pz[3 * HID];
__device__ float g_pred[3 * HID];
__device__ float g_delta[NLV * HID];
__device__ float g_mdelta[NLV * HID];
__device__ float g_gop[HID];
__device__ float g_b2d[NLV * OUTD];

// bf16 split buffers (16B aligned for cp.async)
__device__ __align__(16) __nv_bfloat16 g_A2h[(size_t)NC * K2_H];
__device__ __align__(16) __nv_bfloat16 g_A2m[(size_t)NC * K2_M];
__device__ __align__(16) __nv_bfloat16 g_zab2[(size_t)NC * K2_Z];
__device__ __align__(16) __nv_bfloat16 g_W2hh[(size_t)NLV * G3 * K2_H];
__device__ __align__(16) __nv_bfloat16 g_W2ih[(size_t)NLV * G3 * K2_M];
__device__ __align__(16) __nv_bfloat16 g_W1b2[(size_t)NLV * 256 * K2_H];
__device__ __align__(16) __nv_bfloat16 g_W2b2[(size_t)NLV * OUTD * K2_Z];

// ================= mma.sync GEMM =================
#define BM 128
#define BN 128
#define BK 32
#define PROW 40                        // padded row length in bf16 (80 bytes)
#define STAGE ((BM + BN) * PROW)       // elements per stage

__device__ __forceinline__ void cp16(uint32_t dst, const void* src)
{
    asm volatile("cp.async.cg.shared.global [%0], [%1], 16;" :: "r"(dst), "l"(src));
}
__device__ __forceinline__ void cp_commit() { asm volatile("cp.async.commit_group;"); }
template<int N> __device__ __forceinline__ void cp_wait()
{
    asm volatile("cp.async.wait_group %0;" :: "n"(N));
}
__device__ __forceinline__ void ldsm4(uint32_t& r0, uint32_t& r1, uint32_t& r2, uint32_t& r3,
                                      uint32_t addr)
{
    asm volatile("ldmatrix.sync.aligned.m8n8.x4.shared.b16 {%0,%1,%2,%3}, [%4];"
                 : "=r"(r0), "=r"(r1), "=r"(r2), "=r"(r3) : "r"(addr));
}
__device__ __forceinline__ void mma16816(float* d, const uint32_t* a, const uint32_t* b)
{
    asm volatile("mma.sync.aligned.m16n8k16.row.col.f32.bf16.bf16.f32 "
                 "{%0,%1,%2,%3}, {%4,%5,%6,%7}, {%8,%9}, {%0,%1,%2,%3};"
                 : "+f"(d[0]), "+f"(d[1]), "+f"(d[2]), "+f"(d[3])
                 : "r"(a[0]), "r"(a[1]), "r"(a[2]), "r"(a[3]), "r"(b[0]), "r"(b[1]));
}

// C[lvl][m0.., n0..] = act( A2[lvl] @ B2[lvl]^T + bias )
// A2: [M,K2] bf16 row-major; B2: [N,K2] bf16 row-major; K2 % 32 == 0, M,N % 128 == 0
__global__ void __launch_bounds__(256)
tgemm(const __nv_bfloat16* __restrict__ A, long sA,
      const __nv_bfloat16* __restrict__ B, long sB,
      float* __restrict__ C, int ldc, long sC,
      int K2, const float* __restrict__ bias, int sBias, int act)
{
    __shared__ __align__(16) __nv_bfloat16 smem[2 * STAGE];
    const int tid = threadIdx.x, wid = tid >> 5, lane = tid & 31;
    const int m0 = blockIdx.y * BM, n0 = blockIdx.x * BN, lvl = blockIdx.z;
    A += (long)lvl * sA + (long)m0 * K2;
    B += (long)lvl * sB + (long)n0 * K2;
    C += (long)lvl * sC;
    const float* bp = bias ? bias + (long)lvl * sBias + n0 : nullptr;

    const int wm = (wid >> 2) * 64, wn = (wid & 3) * 32;
    const uint32_t sb = (uint32_t)__cvta_generic_to_shared(smem);

    float acc[4][4][4] = {};

    const int nt = K2 / BK;
    const int row = tid >> 2, ch = tid & 3;   // 64 rows per pass, 4 chunks/row

    auto load_tile = [&](int kt, int s) {
        const __nv_bfloat16* Ag = A + kt * BK;
        const __nv_bfloat16* Bg = B + kt * BK;
        uint32_t base = sb + s * (STAGE * 2);
#pragma unroll
        for (int it = 0; it < 2; it++) {
            int r = row + it * 64;
            uint32_t o = (uint32_t)(r * PROW + ch * 8) * 2;
            cp16(base + o, Ag + (long)r * K2 + ch * 8);
            cp16(base + BM * PROW * 2 + o, Bg + (long)r * K2 + ch * 8);
        }
    };

    load_tile(0, 0);
    cp_commit();

    for (int kt = 0; kt < nt; kt++) {
        int cur = kt & 1;
        if (kt + 1 < nt) { load_tile(kt + 1, cur ^ 1); cp_commit(); cp_wait<1>(); }
        else             { cp_wait<0>(); }
        __syncthreads();

        uint32_t as = sb + cur * (STAGE * 2);
        uint32_t bs = as + BM * PROW * 2;
#pragma unroll
        for (int ks = 0; ks < 2; ks++) {
            int k0 = ks * 16;
            uint32_t b[4][2];
#pragma unroll
            for (int nb2 = 0; nb2 < 2; nb2++) {
                int n  = wn + nb2 * 16 + (lane & 7) + ((lane & 16) ? 8 : 0);
                int kk = k0 + ((lane & 8) ? 8 : 0);
                uint32_t r0, r1, r2, r3;
                ldsm4(r0, r1, r2, r3, bs + (uint32_t)(n * PROW + kk) * 2);
                b[nb2 * 2][0] = r0; b[nb2 * 2][1] = r1;
                b[nb2 * 2 + 1][0] = r2; b[nb2 * 2 + 1][1] = r3;
            }
#pragma unroll
            for (int mi = 0; mi < 4; mi++) {
                int r  = wm + mi * 16 + (lane & 7) + ((lane & 8) ? 8 : 0);
                int kk = k0 + ((lane & 16) ? 8 : 0);
                uint32_t a[4];
                ldsm4(a[0], a[1], a[2], a[3], as + (uint32_t)(r * PROW + kk) * 2);
#pragma unroll
                for (int ni = 0; ni < 4; ni++)
                    mma16816(acc[mi][ni], a, b[ni]);
            }
        }
        __syncthreads();
    }

    // epilogue
    const int tr = lane >> 2, tc = (lane & 3) * 2;
#pragma unroll
    for (int mi = 0; mi < 4; mi++) {
        int r = m0 + wm + mi * 16 + tr;
#pragma unroll
        for (int ni = 0; ni < 4; ni++) {
            int c  = wn + ni * 8 + tc;
            float b0 = bp ? bp[c] : 0.f, b1 = bp ? bp[c + 1] : 0.f;
            float v0 = acc[mi][ni][0] + b0, v1 = acc[mi][ni][1] + b1;
            float v2 = acc[mi][ni][2] + b0, v3 = acc[mi][ni][3] + b1;
            if (act) { v0 = fmaxf(v0, 0.f); v1 = fmaxf(v1, 0.f);
                       v2 = fmaxf(v2, 0.f); v3 = fmaxf(v3, 0.f); }
            C[(long)r * ldc + n0 + c]           = v0;
            C[(long)r * ldc + n0 + c + 1]       = v1;
            C[(long)(r + 8) * ldc + n0 + c]     = v2;
            C[(long)(r + 8) * ldc + n0 + c + 1] = v3;
        }
    }
}

// ================= conversion kernels =================
// MODE 0 (A-side): [hi | hi | lo]   MODE 1 (B-side): [hi | lo | hi]
template<int MODE>
__global__ void split3_k(const float* __restrict__ src, int lds,
                         __nv_bfloat16* __restrict__ dst, int K, int Kp, long total)
{
    long i = (long)blockIdx.x * 256 + threadIdx.x;
    if (i >= total) return;
    long r = i / Kp; int k = (int)(i - r * Kp);
    float v = (k < K) ? src[r * (long)lds + k] : 0.f;
    __nv_bfloat16 hi = __float2bfloat16(v);
    __nv_bfloat16 lo = __float2bfloat16(v - __bfloat162float(hi));
    __nv_bfloat16* d = dst + r * (3L * Kp);
    if (MODE == 0) { d[k] = hi; d[Kp + k] = hi; d[2L * Kp + k] = lo; }
    else           { d[k] = hi; d[Kp + k] = lo; d[2L * Kp + k] = hi; }
}

__global__ void convW1_k(const float* __restrict__ ea, const float* __restrict__ eg)
{
    long i = (long)blockIdx.x * 256 + threadIdx.x;          // 4*256*1024
    if (i >= 4L * 256 * 1024) return;
    int k = (int)(i & 1023); long t = i >> 10; int n = (int)(t & 255); int l = (int)(t >> 8);
    const float* src = ((n < 128) ? ea : eg) + (long)l * (IND + HID) * MLPD;
    float v = src[(long)(IND + k) * MLPD + (n & 127)];
    __nv_bfloat16 hi = __float2bfloat16(v);
    __nv_bfloat16 lo = __float2bfloat16(v - __bfloat162float(hi));
    __nv_bfloat16* d = g_W1b2 + ((long)l * 256 + n) * K2_H;
    d[k] = hi; d[1024 + k] = lo; d[2048 + k] = hi;
}

__global__ void convW2_k(const float* __restrict__ W2a, const float* __restrict__ W2g)
{
    long i = (long)blockIdx.x * 256 + threadIdx.x;          // 4*512*256
    if (i >= 4L * 512 * 256) return;
    int k = (int)(i & 255); long t = i >> 8; int n = (int)(t & 511); int l = (int)(t >> 9);
    float v = (k < 128) ? W2a[(long)l * MLPD * OUTD + (long)k * OUTD + n]
                        : -W2g[(long)l * MLPD * OUTD + (long)(k - 128) * OUTD + n];
    __nv_bfloat16 hi = __float2bfloat16(v);
    __nv_bfloat16 lo = __float2bfloat16(v - __bfloat162float(hi));
    __nv_bfloat16* d = g_W2b2 + ((long)l * 512 + n) * K2_Z;
    d[k] = hi; d[256 + k] = lo; d[512 + k] = hi;
}

__global__ void b2diff_k(const float* __restrict__ a, const float* __restrict__ g)
{
    int i = blockIdx.x * 256 + threadIdx.x;
    g_b2d[i] = a[i] - g[i];
}

// ================= small fp32 kernels =================
__global__ void xa_kernel(const float* __restrict__ x,
                          const float* __restrict__ eaW1, const float* __restrict__ eab1,
                          const float* __restrict__ egW1, const float* __restrict__ egb1)
{
    int which = blockIdx.x, l = blockIdx.y, m = threadIdx.x;
    const float* W = (which ? egW1 : eaW1) + (size_t)l * (IND + HID) * MLPD;
    const float* b = (which ? egb1 : eab1) + l * MLPD;
    float acc = b[m];
    for (int i = 0; i < IND; i++) acc = fmaf(x[i], W[(size_t)i * MLPD + m], acc);
    g_xa2[l * 256 + which * 128 + m] = acc;
}

__global__ void tension_kernel()
{
    int c = blockIdx.x, t = threadIdx.x;
    const float* row = g_out + (size_t)c * MEMK;
    float s = 0.f;
#pragma unroll
    for (int q = 0; q < 4; q++) { float v = row[t + 128 * q]; s = fmaf(v, v, s); }
    __shared__ float sm[128];
    sm[t] = s; __syncthreads();
    for (int o = 64; o > 0; o >>= 1) { if (t < o) sm[t] += sm[t + o]; __syncthreads(); }
    if (t == 0) g_out[(size_t)c * MEMK + OUTD] = sm[0] * (1.f / OUTD);
}

__global__ void gate_kernel(const float* __restrict__ hid)
{
    int idx = blockIdx.x * blockDim.x + threadIdx.x;
    int c = idx >> 10, j = idx & 1023;
    size_t base = (size_t)c * G3;
    float ir = g_gi[base + j], iz = g_gi[base + HID + j], inn = g_gi[base + 2 * HID + j];
    float hr = g_gh[base + j], hz = g_gh[base + HID + j], hn  = g_gh[base + 2 * HID + j];
    float r = 1.f / (1.f + expf(-(ir + hr)));
    float z = 1.f / (1.f + expf(-(iz + hz)));
    float n = tanhf(inn + r * hn);
    g_newh[idx] = (1.f - z) * n + z * hid[idx];
}

__global__ void colsum_kernel()
{
    int l = blockIdx.y, j = blockIdx.x * 128 + threadIdx.x;
    const float* p = g_newh + ((size_t)l * CPL) * HID + j;
    float s = 0.f;
    for (int c = 0; c < CPL; c++) s += p[(size_t)c * HID];
    g_lm[l * HID + j] = s * (1.f / CPL);
}

__global__ void pred1_kernel(const float* __restrict__ W1, const float* __restrict__ b1)
{
    int l = blockIdx.x, t = threadIdx.x;
    float acc[4];
#pragma unroll
    for (int q = 0; q < 4; q++) acc[q] = b1[l * HID + t + 256 * q];
    const float* lm = g_lm + (l + 1) * HID;
    const float* W  = W1 + (size_t)l * HID * HID;
    for (int i = 0; i < HID; i++) {
        float a = lm[i];
#pragma unroll
        for (int q = 0; q < 4; q++) acc[q] = fmaf(a, W[(size_t)i * HID + t + 256 * q], acc[q]);
    }
#pragma unroll
    for (int q = 0; q < 4; q++) g_pz[l * HID + t + 256 * q] = fmaxf(acc[q], 0.f);
}

__global__ void pred2_kernel(const float* __restrict__ W2, const float* __restrict__ b2)
{
    int l = blockIdx.x, t = threadIdx.x;
    float acc[4];
#pragma unroll
    for (int q = 0; q < 4; q++) acc[q] = b2[l * HID + t + 256 * q];
    const float* pz = g_pz + l * HID;
    const float* W  = W2 + (size_t)l * HID * HID;
    for (int i = 0; i < HID; i++) {
        float a = pz[i];
#pragma unroll
        for (int q = 0; q < 4; q++) acc[q] = fmaf(a, W[(size_t)i * HID + t + 256 * q], acc[q]);
    }
#pragma unroll
    for (int q = 0; q < 4; q++) g_pred[l * HID + t + 256 * q] = acc[q];
}

__global__ void finalize_kernel()
{
    int j = threadIdx.x;
    float lm0 = g_lm[j], lm1 = g_lm[HID + j], lm2 = g_lm[2 * HID + j], lm3 = g_lm[3 * HID + j];
    float pe0 = (g_pred[j] - lm0) * 0.05f;
    float pe1 = (g_pred[HID + j] - lm1) * 0.05f;
    float pe2 = (g_pred[2 * HID + j] - lm2) * 0.05f;
    float d0 = pe0, d1 = pe1 - 0.5f * pe0, d2 = pe2 - 0.5f * pe1, d3 = -0.5f * pe2;
    g_delta[j] = d0; g_delta[HID + j] = d1; g_delta[2 * HID + j] = d2; g_delta[3 * HID + j] = d3;
    float m0 = lm0 + d0, m1 = lm1 + d1, m2 = lm2 + d2, m3 = lm3 + d3;
    g_mdelta[j] = m0; g_mdelta[HID + j] = m1; g_mdelta[2 * HID + j] = m2; g_mdelta[3 * HID + j] = m3;
    g_gop[j] = (m0 + m1 + m2 + m3) * 0.25f;
}

__global__ void hh_kernel(float* __restrict__ out, const int* __restrict__ stepp)
{
    int idx = blockIdx.x * blockDim.x + threadIdx.x;
    int c = idx >> 10, j = idx & 1023;
    int l = c >> 10, cl = c & 1023;
    float d = g_delta[l * HID + j];
    float v = 0.7225f * (g_newh[idx] + d) + 0.2775f * g_mdelta[l * HID + j];
    if (*stepp > 5 && cl < (CPL / 4)) v = 0.85f * v + 0.15f * g_gop[j];
    out[513 + idx] = v;
}

__global__ void combined_kernel(const float* __restrict__ W, const float* __restrict__ b,
                                float* __restrict__ out)
{
    int n = blockIdx.x * blockDim.x + threadIdx.x;
    float acc = b[n];
    for (int i = 0; i < NLV * HID; i++) acc = fmaf(g_lm[i], W[(size_t)i * OUTD + n], acc);
    out[n] = acc;
}

__global__ void avgten_kernel(float* __restrict__ out)
{
    __shared__ float sm[1024];
    int t = threadIdx.x;
    float s = 0.f;
#pragma unroll
    for (int q = 0; q < 4; q++) s += g_out[(size_t)(t + 1024 * q) * MEMK + OUTD];
    sm[t] = s; __syncthreads();
    for (int o = 512; o > 0; o >>= 1) { if (t < o) sm[t] += sm[t + o]; __syncthreads(); }
    if (t == 0) out[OUTD] = sm[0] * (1.f / NC);
}

// ================= host =================
template<class T> static T* sym(const T& s)
{
    void* p = nullptr;
    cudaGetSymbolAddress(&p, s);
    return (T*)p;
}

extern "C" void kernel_launch(void* const* d_in, const int* in_sizes, int n_in,
                              void* d_out, int out_size)
{
    const float* x     = (const float*)d_in[0];
    const float* hid   = (const float*)d_in[1];
    const float* eaW1  = (const float*)d_in[2];
    const float* eab1  = (const float*)d_in[3];
    const float* eaW2  = (const float*)d_in[4];
    const float* eab2  = (const float*)d_in[5];
    const float* egW1  = (const float*)d_in[6];
    const float* egb1  = (const float*)d_in[7];
    const float* egW2  = (const float*)d_in[8];
    const float* egb2  = (const float*)d_in[9];
    const float* Wih   = (const float*)d_in[10];
    const float* Whh   = (const float*)d_in[11];
    const float* bih   = (const float*)d_in[12];
    const float* bhh   = (const float*)d_in[13];
    const float* pW1   = (const float*)d_in[14];
    const float* pb1   = (const float*)d_in[15];
    const float* pW2   = (const float*)d_in[16];
    const float* pb2   = (const float*)d_in[17];
    const float* peiW  = (const float*)d_in[18];
    const float* peib  = (const float*)d_in[19];
    const int*   stepp = (const int*)d_in[20];
    float* out = (float*)d_out;

    float* zab  = sym(g_zab[0]);
    float* outb = sym(g_out[0]);
    float* gi   = sym(g_gi[0]);
    float* gh   = sym(g_gh[0]);
    float* xa2  = sym(g_xa2[0]);
    float* b2d  = sym(g_b2d[0]);
    __nv_bfloat16* A2h  = sym(g_A2h[0]);
    __nv_bfloat16* A2m  = sym(g_A2m[0]);
    __nv_bfloat16* zab2 = sym(g_zab2[0]);
    __nv_bfloat16* W2hh = sym(g_W2hh[0]);
    __nv_bfloat16* W2ih = sym(g_W2ih[0]);
    __nv_bfloat16* W1b2 = sym(g_W1b2[0]);
    __nv_bfloat16* W2b2 = sym(g_W2b2[0]);

    auto nb = [](long total) { return (unsigned)((total + 255) / 256); };

    // ---- conversions ----
    xa_kernel<<<dim3(2, NLV), 128>>>(x, eaW1, eab1, egW1, egb1);
    convW1_k<<<nb(4L * 256 * 1024), 256>>>(eaW1, egW1);
    convW2_k<<<nb(4L * 512 * 256), 256>>>(eaW2, egW2);
    b2diff_k<<<8, 256>>>(eab2, egb2);
    split3_k<0><<<nb((long)NC * 1024), 256>>>(hid, HID, A2h, 1024, 1024, (long)NC * 1024);
    split3_k<1><<<nb((long)NLV * G3 * 1024), 256>>>(Whh, 1024, W2hh, 1024, 1024, (long)NLV * G3 * 1024);
    split3_k<1><<<nb((long)NLV * G3 * KP_M), 256>>>(Wih, MEMK, W2ih, MEMK, KP_M, (long)NLV * G3 * KP_M);

    // ---- MLP1: [za|zg] = relu(h @ [W1a;W1g]^T + xa2) ----
    tgemm<<<dim3(256 / BN, CPL / BM, NLV), 256>>>(
        A2h, (long)CPL * K2_H, W1b2, 256L * K2_H,
        zab, 256, (long)CPL * 256, K2_H, xa2, 256, 1);

    // ---- MLP2: out = [za|zg] @ [W2a;-W2g]^T + (b2a-b2g) ----
    split3_k<0><<<nb((long)NC * 256), 256>>>(zab, 256, zab2, 256, 256, (long)NC * 256);
    tgemm<<<dim3(OUTD / BN, CPL / BM, NLV), 256>>>(
        zab2, (long)CPL * K2_Z, W2b2, (long)OUTD * K2_Z,
        outb, MEMK, (long)CPL * MEMK, K2_Z, b2d, OUTD, 0);

    // ---- tension + mem_in split ----
    tension_kernel<<<NC, 128>>>();
    split3_k<0><<<nb((long)NC * KP_M), 256>>>(outb, MEMK, A2m, MEMK, KP_M, (long)NC * KP_M);

    // ---- GRU gi / gh ----
    tgemm<<<dim3(G3 / BN, CPL / BM, NLV), 256>>>(
        A2m, (long)CPL * K2_M, W2ih, (long)G3 * K2_M,
        gi, G3, (long)CPL * G3, K2_M, bih, G3, 0);
    tgemm<<<dim3(G3 / BN, CPL / BM, NLV), 256>>>(
        A2h, (long)CPL * K2_H, W2hh, (long)G3 * K2_H,
        gh, G3, (long)CPL * G3, K2_H, bhh, G3, 0);

    // ---- gates + epilogue chain ----
    gate_kernel<<<(NC * HID) / 256, 256>>>(hid);
    colsum_kernel<<<dim3(HID / 128, NLV), 128>>>();
    pred1_kernel<<<3, 256>>>(pW1, pb1);
    pred2_kernel<<<3, 256>>>(pW2, pb2);
    finalize_kernel<<<1, 1024>>>();
    hh_kernel<<<(NC * HID) / 256, 256>>>(out, stepp);
    combined_kernel<<<OUTD / 256, 256>>>(peiW, peib, out);
    avgten_kernel<<<1, 1024>>>(out);
}

// round 5
// speedup vs baseline: 3.1436x; 2.1930x over previous
#include <cuda_runtime.h>
#include <cuda_bf16.h>
#include <cstdint>
#include <math.h>

#define NLV  4
#define CPL  1024
#define NC   4096
#define IND  512
#define HID  1024
#define OUTD 512
#define MLPD 128
#define G3   3072
#define MEMK 513

#define K2_H   3072
#define KP_M   576
#define K2_M   1728
#define K2_Z   768

// ---------------- scratch ----------------
__device__ float g_xa2[NLV * 256];
__device__ float g_xap[2 * NLV * 4 * 128];
__device__ float g_zab[NC * 256];
__device__ float g_out[NC * MEMK];
__device__ float g_gi[(size_t)NC * G3];
__device__ float g_gh[(size_t)NC * G3];
__device__ float g_newh[NC * HID];
__device__ float g_lm[NLV * HID];
__device__ float g_cs[NLV * 8 * HID];
__device__ float g_pz[3 * HID];
__device__ float g_pp[3 * 16 * HID];
__device__ float g_pp2[3 * 16 * HID];
__device__ float g_pred[3 * HID];
__device__ float g_delta[NLV * HID];
__device__ float g_mdelta[NLV * HID];
__device__ float g_gop[HID];
__device__ float g_b2d[NLV * OUTD];
__device__ float g_cp[16 * OUTD];

__device__ __align__(16) __nv_bfloat16 g_A2h[(size_t)NC * K2_H];
__device__ __align__(16) __nv_bfloat16 g_A2m[(size_t)NC * K2_M];
__device__ __align__(16) __nv_bfloat16 g_zab2[(size_t)NC * K2_Z];
__device__ __align__(16) __nv_bfloat16 g_W2hh[(size_t)NLV * G3 * K2_H];
__device__ __align__(16) __nv_bfloat16 g_W2ih[(size_t)NLV * G3 * K2_M];
__device__ __align__(16) __nv_bfloat16 g_W1b2[(size_t)NLV * 256 * K2_H];
__device__ __align__(16) __nv_bfloat16 g_W2b2[(size_t)NLV * OUTD * K2_Z];

// ================= mma.sync GEMM (BK=64, 3-stage cp.async) =================
#define BM 128
#define BN 128
#define BK 64
#define PROW 72                          // padded row in bf16 (144 B)
#define STG_B ((BM + BN) * PROW * 2)     // bytes per stage = 36864
#define BOFF  (BM * PROW * 2)

__device__ __forceinline__ void cp16(uint32_t dst, const void* src)
{
    asm volatile("cp.async.cg.shared.global [%0], [%1], 16;" :: "r"(dst), "l"(src));
}
__device__ __forceinline__ void cp_commit() { asm volatile("cp.async.commit_group;"); }
template<int N> __device__ __forceinline__ void cp_wait()
{
    asm volatile("cp.async.wait_group %0;" :: "n"(N));
}
__device__ __forceinline__ void ldsm4(uint32_t& r0, uint32_t& r1, uint32_t& r2, uint32_t& r3,
                                      uint32_t addr)
{
    asm volatile("ldmatrix.sync.aligned.m8n8.x4.shared.b16 {%0,%1,%2,%3}, [%4];"
                 : "=r"(r0), "=r"(r1), "=r"(r2), "=r"(r3) : "r"(addr));
}
__device__ __forceinline__ void mma16816(float* d, const uint32_t* a, const uint32_t* b)
{
    asm volatile("mma.sync.aligned.m16n8k16.row.col.f32.bf16.bf16.f32 "
                 "{%0,%1,%2,%3}, {%4,%5,%6,%7}, {%8,%9}, {%0,%1,%2,%3};"
                 : "+f"(d[0]), "+f"(d[1]), "+f"(d[2]), "+f"(d[3])
                 : "r"(a[0]), "r"(a[1]), "r"(a[2]), "r"(a[3]), "r"(b[0]), "r"(b[1]));
}

__global__ void __launch_bounds__(256, 2)
tgemm(const __nv_bfloat16* __restrict__ A, long sA,
      const __nv_bfloat16* __restrict__ B, long sB,
      float* __restrict__ C, int ldc, long sC,
      int K2, const float* __restrict__ bias, int sBias, int act)
{
    extern __shared__ __align__(16) char smem[];
    const int tid = threadIdx.x, wid = tid >> 5, lane = tid & 31;
    const int m0 = blockIdx.y * BM, n0 = blockIdx.x * BN, lvl = blockIdx.z;
    A += (long)lvl * sA + (long)m0 * K2;
    B += (long)lvl * sB + (long)n0 * K2;
    C += (long)lvl * sC;
    const float* bp = bias ? bias + (long)lvl * sBias + n0 : nullptr;

    const int wm = (wid >> 2) * 64, wn = (wid & 3) * 32;
    const uint32_t sb = (uint32_t)__cvta_generic_to_shared(smem);

    float acc[4][4][4] = {};
    const int nt = K2 / BK;
    const int rrow = tid >> 3, rch = tid & 7;   // 32 rows/pass, 8 chunks/row

    auto load_tile = [&](int kt, int s) {
        const __nv_bfloat16* Ag = A + kt * BK;
        const __nv_bfloat16* Bg = B + kt * BK;
        uint32_t base = sb + (uint32_t)s * STG_B;
#pragma unroll
        for (int it = 0; it < 4; it++) {
            int r = rrow + it * 32;
            uint32_t o = (uint32_t)(r * PROW + rch * 8) * 2;
            cp16(base + o, Ag + (long)r * K2 + rch * 8);
        }
#pragma unroll
        for (int it = 0; it < 4; it++) {
            int r = rrow + it * 32;
            uint32_t o = (uint32_t)(r * PROW + rch * 8) * 2;
            cp16(base + BOFF + o, Bg + (long)r * K2 + rch * 8);
        }
    };

    load_tile(0, 0); cp_commit();
    load_tile(1, 1); cp_commit();

    int st = 0;
    for (int kt = 0; kt < nt; kt++) {
        cp_wait<1>();
        __syncthreads();
        if (kt + 2 < nt) {
            int s2 = st + 2; if (s2 >= 3) s2 -= 3;
            load_tile(kt + 2, s2); cp_commit();
        }
        uint32_t as = sb + (uint32_t)st * STG_B;
        uint32_t bs = as + BOFF;
#pragma unroll
        for (int ks = 0; ks < 4; ks++) {
            int k0 = ks * 16;
            uint32_t b[4][2];
#pragma unroll
            for (int nb2 = 0; nb2 < 2; nb2++) {
                int n  = wn + nb2 * 16 + (lane & 7) + ((lane & 16) ? 8 : 0);
                int kk = k0 + ((lane & 8) ? 8 : 0);
                uint32_t r0, r1, r2, r3;
                ldsm4(r0, r1, r2, r3, bs + (uint32_t)(n * PROW + kk) * 2);
                b[nb2 * 2][0] = r0; b[nb2 * 2][1] = r1;
                b[nb2 * 2 + 1][0] = r2; b[nb2 * 2 + 1][1] = r3;
            }
#pragma unroll
            for (int mi = 0; mi < 4; mi++) {
                int r  = wm + mi * 16 + (lane & 7) + ((lane & 8) ? 8 : 0);
                int kk = k0 + ((lane & 16) ? 8 : 0);
                uint32_t a[4];
                ldsm4(a[0], a[1], a[2], a[3], as + (uint32_t)(r * PROW + kk) * 2);
#pragma unroll
                for (int ni = 0; ni < 4; ni++)
                    mma16816(acc[mi][ni], a, b[ni]);
            }
        }
        if (++st == 3) st = 0;
    }

    const int tr = lane >> 2, tc = (lane & 3) * 2;
#pragma unroll
    for (int mi = 0; mi < 4; mi++) {
        int r = m0 + wm + mi * 16 + tr;
#pragma unroll
        for (int ni = 0; ni < 4; ni++) {
            int c  = wn + ni * 8 + tc;
            float b0 = bp ? bp[c] : 0.f, b1 = bp ? bp[c + 1] : 0.f;
            float v0 = acc[mi][ni][0] + b0, v1 = acc[mi][ni][1] + b1;
            float v2 = acc[mi][ni][2] + b0, v3 = acc[mi][ni][3] + b1;
            if (act) { v0 = fmaxf(v0, 0.f); v1 = fmaxf(v1, 0.f);
                       v2 = fmaxf(v2, 0.f); v3 = fmaxf(v3, 0.f); }
            C[(long)r * ldc + n0 + c]           = v0;
            C[(long)r * ldc + n0 + c + 1]       = v1;
            C[(long)(r + 8) * ldc + n0 + c]     = v2;
            C[(long)(r + 8) * ldc + n0 + c + 1] = v3;
        }
    }
}

// ================= conversions =================
// Vectorized split (contiguous rows, K%8==0). MODE0: [hi|hi|lo]  MODE1: [hi|lo|hi]
template<int MODE>
__global__ void split3v_k(const float* __restrict__ src, __nv_bfloat16* __restrict__ dst,
                          int K, long total8)
{
    long i = (long)blockIdx.x * 256 + threadIdx.x;
    if (i >= total8) return;
    int kc = K >> 3;
    long r = i / kc; int k = (int)(i - r * kc) * 8;
    const float* s = src + r * (long)K + k;
    float4 v0 = *(const float4*)s;
    float4 v1 = *(const float4*)(s + 4);
    float vv[8] = {v0.x, v0.y, v0.z, v0.w, v1.x, v1.y, v1.z, v1.w};
    union { __nv_bfloat162 h2[4]; uint4 u; } H, L;
#pragma unroll
    for (int j = 0; j < 4; j++) {
        float a = vv[2 * j], b = vv[2 * j + 1];
        __nv_bfloat16 ah = __float2bfloat16(a), bh = __float2bfloat16(b);
        __nv_bfloat16 al = __float2bfloat16(a - __bfloat162float(ah));
        __nv_bfloat16 bl = __float2bfloat16(b - __bfloat162float(bh));
        H.h2[j] = __nv_bfloat162(ah, bh);
        L.h2[j] = __nv_bfloat162(al, bl);
    }
    __nv_bfloat16* d = dst + r * (3L * K) + k;
    *(uint4*)d = H.u;
    if (MODE == 0) { *(uint4*)(d + K) = H.u; *(uint4*)(d + 2L * K) = L.u; }
    else           { *(uint4*)(d + K) = L.u; *(uint4*)(d + 2L * K) = H.u; }
}

// scalar split for non-aligned lds (MEMK rows)
template<int MODE>
__global__ void split3_k(const float* __restrict__ src, int lds,
                         __nv_bfloat16* __restrict__ dst, int K, int Kp, long total)
{
    long i = (long)blockIdx.x * 256 + threadIdx.x;
    if (i >= total) return;
    long r = i / Kp; int k = (int)(i - r * Kp);
    float v = (k < K) ? src[r * (long)lds + k] : 0.f;
    __nv_bfloat16 hi = __float2bfloat16(v);
    __nv_bfloat16 lo = __float2bfloat16(v - __bfloat162float(hi));
    __nv_bfloat16* d = dst + r * (3L * Kp);
    if (MODE == 0) { d[k] = hi; d[Kp + k] = hi; d[2L * Kp + k] = lo; }
    else           { d[k] = hi; d[Kp + k] = lo; d[2L * Kp + k] = hi; }
}

__global__ void convW1_k(const float* __restrict__ ea, const float* __restrict__ eg)
{
    long i = (long)blockIdx.x * 256 + threadIdx.x;
    if (i >= 4L * 256 * 1024) return;
    int k = (int)(i & 1023); long t = i >> 10; int n = (int)(t & 255); int l = (int)(t >> 8);
    const float* src = ((n < 128) ? ea : eg) + (long)l * (IND + HID) * MLPD;
    float v = src[(long)(IND + k) * MLPD + (n & 127)];
    __nv_bfloat16 hi = __float2bfloat16(v);
    __nv_bfloat16 lo = __float2bfloat16(v - __bfloat162float(hi));
    __nv_bfloat16* d = g_W1b2 + ((long)l * 256 + n) * K2_H;
    d[k] = hi; d[1024 + k] = lo; d[2048 + k] = hi;
}

__global__ void convW2_k(const float* __restrict__ W2a, const float* __restrict__ W2g)
{
    long i = (long)blockIdx.x * 256 + threadIdx.x;
    if (i >= 4L * 512 * 256) return;
    int k = (int)(i & 255); long t = i >> 8; int n = (int)(t & 511); int l = (int)(t >> 9);
    float v = (k < 128) ? W2a[(long)l * MLPD * OUTD + (long)k * OUTD + n]
                        : -W2g[(long)l * MLPD * OUTD + (long)(k - 128) * OUTD + n];
    __nv_bfloat16 hi = __float2bfloat16(v);
    __nv_bfloat16 lo = __float2bfloat16(v - __bfloat162float(hi));
    __nv_bfloat16* d = g_W2b2 + ((long)l * 512 + n) * K2_Z;
    d[k] = hi; d[256 + k] = lo; d[512 + k] = hi;
}

__global__ void b2diff_k(const float* __restrict__ a, const float* __restrict__ g)
{
    int i = blockIdx.x * 256 + threadIdx.x;
    g_b2d[i] = a[i] - g[i];
}

// ================= tail kernels (split-K, deterministic) =================
__global__ void xa_part(const float* __restrict__ x,
                        const float* __restrict__ eaW1, const float* __restrict__ egW1)
{
    int ks = blockIdx.x, l = blockIdx.y, which = blockIdx.z, t = threadIdx.x;
    const float* W = (which ? egW1 : eaW1) + (size_t)l * (IND + HID) * MLPD
                     + (size_t)ks * 128 * MLPD;
    const float* xs = x + ks * 128;
    float s = 0.f;
    for (int i = 0; i < 128; i++) s = fmaf(xs[i], W[(size_t)i * MLPD + t], s);
    g_xap[((which * NLV + l) * 4 + ks) * 128 + t] = s;
}
__global__ void xa_red(const float* __restrict__ eab1, const float* __restrict__ egb1)
{
    int l = blockIdx.x, which = blockIdx.y, t = threadIdx.x;
    const float* b = (which ? egb1 : eab1) + l * MLPD;
    float s = b[t];
    for (int ks = 0; ks < 4; ks++) s += g_xap[((which * NLV + l) * 4 + ks) * 128 + t];
    g_xa2[l * 256 + which * 128 + t] = s;
}

__global__ void tension_kernel()
{
    int c = blockIdx.x, t = threadIdx.x;
    const float* row = g_out + (size_t)c * MEMK;
    float s = 0.f;
#pragma unroll
    for (int q = 0; q < 4; q++) { float v = row[t + 128 * q]; s = fmaf(v, v, s); }
    __shared__ float sm[128];
    sm[t] = s; __syncthreads();
    for (int o = 64; o > 0; o >>= 1) { if (t < o) sm[t] += sm[t + o]; __syncthreads(); }
    if (t == 0) g_out[(size_t)c * MEMK + OUTD] = sm[0] * (1.f / OUTD);
}

__global__ void gate_kernel(const float* __restrict__ hid)
{
    int i4 = blockIdx.x * 256 + threadIdx.x;          // NC*HID/4
    int c = i4 >> 8, j4 = (i4 & 255) * 4;
    size_t base = (size_t)c * G3 + j4;
    float4 ir = *(const float4*)(g_gi + base);
    float4 iz = *(const float4*)(g_gi + base + HID);
    float4 in = *(const float4*)(g_gi + base + 2 * HID);
    float4 hr = *(const float4*)(g_gh + base);
    float4 hz = *(const float4*)(g_gh + base + HID);
    float4 hn = *(const float4*)(g_gh + base + 2 * HID);
    float4 hv = *(const float4*)(hid + (size_t)c * HID + j4);
    float4 o;
    {
        float r = 1.f / (1.f + expf(-(ir.x + hr.x)));
        float z = 1.f / (1.f + expf(-(iz.x + hz.x)));
        o.x = (1.f - z) * tanhf(in.x + r * hn.x) + z * hv.x;
        r = 1.f / (1.f + expf(-(ir.y + hr.y)));
        z = 1.f / (1.f + expf(-(iz.y + hz.y)));
        o.y = (1.f - z) * tanhf(in.y + r * hn.y) + z * hv.y;
        r = 1.f / (1.f + expf(-(ir.z + hr.z)));
        z = 1.f / (1.f + expf(-(iz.z + hz.z)));
        o.z = (1.f - z) * tanhf(in.z + r * hn.z) + z * hv.z;
        r = 1.f / (1.f + expf(-(ir.w + hr.w)));
        z = 1.f / (1.f + expf(-(iz.w + hz.w)));
        o.w = (1.f - z) * tanhf(in.w + r * hn.w) + z * hv.w;
    }
    *(float4*)(g_newh + (size_t)c * HID + j4) = o;
}

__global__ void colsum_part()
{
    int jb = blockIdx.x, l = blockIdx.y, cs = blockIdx.z, t = threadIdx.x;
    int j = jb * 128 + t;
    const float* p = g_newh + ((size_t)(l * CPL + cs * 128)) * HID + j;
    float s = 0.f;
    for (int c = 0; c < 128; c++) s += p[(size_t)c * HID];
    g_cs[(l * 8 + cs) * HID + j] = s;
}
__global__ void colsum_red()
{
    int jb = blockIdx.x, l = blockIdx.y, t = threadIdx.x;
    int j = jb * 128 + t;
    float s = 0.f;
    for (int cs = 0; cs < 8; cs++) s += g_cs[(l * 8 + cs) * HID + j];
    g_lm[l * HID + j] = s * (1.f / CPL);
}

template<int SRC>   // 0: lm[l+1] -> g_pp, 1: pz[l] -> g_pp2
__global__ void pred_part(const float* __restrict__ W)
{
    int ks = blockIdx.x, l = blockIdx.y, t = threadIdx.x;
    const float* v = (SRC == 0 ? g_lm + (l + 1) * HID : g_pz + l * HID) + ks * 64;
    const float* Wp = W + (size_t)l * HID * HID + (size_t)ks * 64 * HID;
    float acc[4] = {0.f, 0.f, 0.f, 0.f};
    for (int i = 0; i < 64; i++) {
        float a = v[i];
#pragma unroll
        for (int q = 0; q < 4; q++) acc[q] = fmaf(a, Wp[(size_t)i * HID + t + 256 * q], acc[q]);
    }
    float* dst = (SRC == 0 ? g_pp : g_pp2) + (l * 16 + ks) * HID;
#pragma unroll
    for (int q = 0; q < 4; q++) dst[t + 256 * q] = acc[q];
}
template<int SRC>
__global__ void pred_red(const float* __restrict__ b)
{
    int l = blockIdx.x, t = threadIdx.x;
    const float* part = (SRC == 0 ? g_pp : g_pp2) + l * 16 * HID;
#pragma unroll
    for (int q = 0; q < 4; q++) {
        int n = t + 256 * q;
        float s = b[l * HID + n];
        for (int ks = 0; ks < 16; ks++) s += part[ks * HID + n];
        if (SRC == 0) g_pz[l * HID + n] = fmaxf(s, 0.f);
        else          g_pred[l * HID + n] = s;
    }
}

__global__ void finalize_kernel()
{
    int j = threadIdx.x;
    float lm0 = g_lm[j], lm1 = g_lm[HID + j], lm2 = g_lm[2 * HID + j], lm3 = g_lm[3 * HID + j];
    float pe0 = (g_pred[j] - lm0) * 0.05f;
    float pe1 = (g_pred[HID + j] - lm1) * 0.05f;
    float pe2 = (g_pred[2 * HID + j] - lm2) * 0.05f;
    float d0 = pe0, d1 = pe1 - 0.5f * pe0, d2 = pe2 - 0.5f * pe1, d3 = -0.5f * pe2;
    g_delta[j] = d0; g_delta[HID + j] = d1; g_delta[2 * HID + j] = d2; g_delta[3 * HID + j] = d3;
    float m0 = lm0 + d0, m1 = lm1 + d1, m2 = lm2 + d2, m3 = lm3 + d3;
    g_mdelta[j] = m0; g_mdelta[HID + j] = m1; g_mdelta[2 * HID + j] = m2; g_mdelta[3 * HID + j] = m3;
    g_gop[j] = (m0 + m1 + m2 + m3) * 0.25f;
}

__global__ void hh_kernel(float* __restrict__ out, const int* __restrict__ stepp)
{
    int idx = blockIdx.x * blockDim.x + threadIdx.x;
    int c = idx >> 10, j = idx & 1023;
    int l = c >> 10, cl = c & 1023;
    float d = g_delta[l * HID + j];
    float v = 0.7225f * (g_newh[idx] + d) + 0.2775f * g_mdelta[l * HID + j];
    if (*stepp > 5 && cl < (CPL / 4)) v = 0.85f * v + 0.15f * g_gop[j];
    out[513 + idx] = v;
}

__global__ void combined_part(const float* __restrict__ W)
{
    int ks = blockIdx.x, nb = blockIdx.y, t = threadIdx.x;
    int n = nb * 256 + t;
    const float* Wp = W + (size_t)ks * 256 * OUTD;
    const float* lm = g_lm + ks * 256;
    float s = 0.f;
    for (int i = 0; i < 256; i++) s = fmaf(lm[i], Wp[(size_t)i * OUTD + n], s);
    g_cp[ks * OUTD + n] = s;
}
__global__ void combined_red(const float* __restrict__ b, float* __restrict__ out)
{
    int n = blockIdx.x * 256 + threadIdx.x;
    float s = b[n];
    for (int ks = 0; ks < 16; ks++) s += g_cp[ks * OUTD + n];
    out[n] = s;
}

__global__ void avgten_kernel(float* __restrict__ out)
{
    __shared__ float sm[1024];
    int t = threadIdx.x;
    float s = 0.f;
#pragma unroll
    for (int q = 0; q < 4; q++) s += g_out[(size_t)(t + 1024 * q) * MEMK + OUTD];
    sm[t] = s; __syncthreads();
    for (int o = 512; o > 0; o >>= 1) { if (t < o) sm[t] += sm[t + o]; __syncthreads(); }
    if (t == 0) out[OUTD] = sm[0] * (1.f / NC);
}

// ================= host =================
template<class T> static T* sym(const T& s)
{
    void* p = nullptr;
    cudaGetSymbolAddress(&p, s);
    return (T*)p;
}

extern "C" void kernel_launch(void* const* d_in, const int* in_sizes, int n_in,
                              void* d_out, int out_size)
{
    const float* x     = (const float*)d_in[0];
    const float* hid   = (const float*)d_in[1];
    const float* eaW1  = (const float*)d_in[2];
    const float* eab1  = (const float*)d_in[3];
    const float* eaW2  = (const float*)d_in[4];
    const float* eab2  = (const float*)d_in[5];
    const float* egW1  = (const float*)d_in[6];
    const float* egb1  = (const float*)d_in[7];
    const float* egW2  = (const float*)d_in[8];
    const float* egb2  = (const float*)d_in[9];
    const float* Wih   = (const float*)d_in[10];
    const float* Whh   = (const float*)d_in[11];
    const float* bih   = (const float*)d_in[12];
    const float* bhh   = (const float*)d_in[13];
    const float* pW1   = (const float*)d_in[14];
    const float* pb1   = (const float*)d_in[15];
    const float* pW2   = (const float*)d_in[16];
    const float* pb2   = (const float*)d_in[17];
    const float* peiW  = (const float*)d_in[18];
    const float* peib  = (const float*)d_in[19];
    const int*   stepp = (const int*)d_in[20];
    float* out = (float*)d_out;

    cudaFuncSetAttribute(tgemm, cudaFuncAttributeMaxDynamicSharedMemorySize, 3 * STG_B);

    float* zab  = sym(g_zab[0]);
    float* outb = sym(g_out[0]);
    float* gi   = sym(g_gi[0]);
    float* gh   = sym(g_gh[0]);
    float* xa2  = sym(g_xa2[0]);
    float* b2d  = sym(g_b2d[0]);
    __nv_bfloat16* A2h  = sym(g_A2h[0]);
    __nv_bfloat16* A2m  = sym(g_A2m[0]);
    __nv_bfloat16* zab2 = sym(g_zab2[0]);
    __nv_bfloat16* W2hh = sym(g_W2hh[0]);
    __nv_bfloat16* W2ih = sym(g_W2ih[0]);
    __nv_bfloat16* W1b2 = sym(g_W1b2[0]);
    __nv_bfloat16* W2b2 = sym(g_W2b2[0]);

    auto nb = [](long total) { return (unsigned)((total + 255) / 256); };

    // ---- conversions ----
    xa_part<<<dim3(4, NLV, 2), 128>>>(x, eaW1, egW1);
    xa_red<<<dim3(NLV, 2), 128>>>(eab1, egb1);
    convW1_k<<<nb(4L * 256 * 1024), 256>>>(eaW1, egW1);
    convW2_k<<<nb(4L * 512 * 256), 256>>>(eaW2, egW2);
    b2diff_k<<<8, 256>>>(eab2, egb2);
    split3v_k<0><<<nb((long)NC * 1024 / 8), 256>>>(hid, A2h, 1024, (long)NC * 1024 / 8);
    split3v_k<1><<<nb((long)NLV * G3 * 1024 / 8), 256>>>(Whh, W2hh, 1024,
                                                         (long)NLV * G3 * 1024 / 8);
    split3_k<1><<<nb((long)NLV * G3 * KP_M), 256>>>(Wih, MEMK, W2ih, MEMK, KP_M,
                                                    (long)NLV * G3 * KP_M);

    // ---- MLP1 ----
    tgemm<<<dim3(256 / BN, CPL / BM, NLV), 256, 3 * STG_B>>>(
        A2h, (long)CPL * K2_H, W1b2, 256L * K2_H,
        zab, 256, (long)CPL * 256, K2_H, xa2, 256, 1);

    // ---- MLP2 ----
    split3v_k<0><<<nb((long)NC * 256 / 8), 256>>>(zab, zab2, 256, (long)NC * 256 / 8);
    tgemm<<<dim3(OUTD / BN, CPL / BM, NLV), 256, 3 * STG_B>>>(
        zab2, (long)CPL * K2_Z, W2b2, (long)OUTD * K2_Z,
        outb, MEMK, (long)CPL * MEMK, K2_Z, b2d, OUTD, 0);

    // ---- tension + mem_in split ----
    tension_kernel<<<NC, 128>>>();
    split3_k<0><<<nb((long)NC * KP_M), 256>>>(outb, MEMK, A2m, MEMK, KP_M, (long)NC * KP_M);

    // ---- GRU gi / gh ----
    tgemm<<<dim3(G3 / BN, CPL / BM, NLV), 256, 3 * STG_B>>>(
        A2m, (long)CPL * K2_M, W2ih, (long)G3 * K2_M,
        gi, G3, (long)CPL * G3, K2_M, bih, G3, 0);
    tgemm<<<dim3(G3 / BN, CPL / BM, NLV), 256, 3 * STG_B>>>(
        A2h, (long)CPL * K2_H, W2hh, (long)G3 * K2_H,
        gh, G3, (long)CPL * G3, K2_H, bhh, G3, 0);

    // ---- gates + epilogue chain ----
    gate_kernel<<<(NC * HID / 4) / 256, 256>>>(hid);
    colsum_part<<<dim3(8, NLV, 8), 128>>>();
    colsum_red<<<dim3(8, NLV), 128>>>();
    pred_part<0><<<dim3(16, 3), 256>>>(pW1);
    pred_red<0><<<3, 256>>>(pb1);
    pred_part<1><<<dim3(16, 3), 256>>>(pW2);
    pred_red<1><<<3, 256>>>(pb2);
    finalize_kernel<<<1, 1024>>>();
    hh_kernel<<<(NC * HID) / 256, 256>>>(out, stepp);
    combined_part<<<dim3(16, 2), 256>>>(peiW);
    combined_red<<<2, 256>>>(peib, out);
    avgten_kernel<<<1, 1024>>>(out);
}

// round 6
// speedup vs baseline: 3.1926x; 1.0156x over previous
#include <cuda_runtime.h>
#include <cuda_bf16.h>
#include <cstdint>
#include <math.h>

#define NLV  4
#define CPL  1024
#define NC   4096
#define IND  512
#define HID  1024
#define OUTD 512
#define MLPD 128
#define G3   3072
#define MEMK 513

#define KP_M   576   // 513 padded

// ---------------- scratch ----------------
__device__ float g_xa2[NLV * 256];
__device__ float g_xap[2 * NLV * 4 * 128];
__device__ float g_zab[NC * 256];
__device__ float g_out[NC * MEMK];
__device__ float g_gi[(size_t)NC * G3];
__device__ float g_gh[(size_t)NC * G3];
__device__ float g_newh[NC * HID];
__device__ float g_lm[NLV * HID];
__device__ float g_cs[NLV * 8 * HID];
__device__ float g_pz[3 * HID];
__device__ float g_pp[3 * 16 * HID];
__device__ float g_pp2[3 * 16 * HID];
__device__ float g_pred[3 * HID];
__device__ float g_delta[NLV * HID];
__device__ float g_mdelta[NLV * HID];
__device__ float g_gop[HID];
__device__ float g_b2d[NLV * OUTD];
__device__ float g_cp[16 * OUTD];

// [hi|lo] bf16 buffers (row length = 2K)
__device__ __align__(16) __nv_bfloat16 g_A2h[(size_t)NC * 2048];
__device__ __align__(16) __nv_bfloat16 g_A2m[(size_t)NC * 2 * KP_M];
__device__ __align__(16) __nv_bfloat16 g_zab2[(size_t)NC * 512];
__device__ __align__(16) __nv_bfloat16 g_W2hh[(size_t)NLV * G3 * 2048];
__device__ __align__(16) __nv_bfloat16 g_W2ih[(size_t)NLV * G3 * 2 * KP_M];
__device__ __align__(16) __nv_bfloat16 g_W1b2[(size_t)NLV * 256 * 2048];
__device__ __align__(16) __nv_bfloat16 g_W2b2[(size_t)NLV * OUTD * 512];

// ================= mma.sync GEMM (3-phase hi/lo, BK=64, 3-stage) =================
#define BN 128
#define BK 64
#define PROW 72

__device__ __forceinline__ void cp16(uint32_t dst, const void* src)
{
    asm volatile("cp.async.cg.shared.global [%0], [%1], 16;" :: "r"(dst), "l"(src));
}
__device__ __forceinline__ void cp_commit() { asm volatile("cp.async.commit_group;"); }
template<int N> __device__ __forceinline__ void cp_wait()
{
    asm volatile("cp.async.wait_group %0;" :: "n"(N));
}
__device__ __forceinline__ void ldsm4(uint32_t& r0, uint32_t& r1, uint32_t& r2, uint32_t& r3,
                                      uint32_t addr)
{
    asm volatile("ldmatrix.sync.aligned.m8n8.x4.shared.b16 {%0,%1,%2,%3}, [%4];"
                 : "=r"(r0), "=r"(r1), "=r"(r2), "=r"(r3) : "r"(addr));
}
__device__ __forceinline__ void mma16816(float* d, const uint32_t* a, const uint32_t* b)
{
    asm volatile("mma.sync.aligned.m16n8k16.row.col.f32.bf16.bf16.f32 "
                 "{%0,%1,%2,%3}, {%4,%5,%6,%7}, {%8,%9}, {%0,%1,%2,%3};"
                 : "+f"(d[0]), "+f"(d[1]), "+f"(d[2]), "+f"(d[3])
                 : "r"(a[0]), "r"(a[1]), "r"(a[2]), "r"(a[3]), "r"(b[0]), "r"(b[1]));
}

// A: [M, 2K] bf16 [hi|lo]; B: [N, 2K] bf16 [hi|lo].
// Computes sum over 3 phases: Ahi@Bhi^T + Ahi@Blo^T + Alo@Bhi^T (+bias, opt relu)
template<int BMT>
__global__ void __launch_bounds__(256, 2)
tgemm(const __nv_bfloat16* __restrict__ A, long sA,
      const __nv_bfloat16* __restrict__ B, long sB,
      float* __restrict__ C, int ldc, long sC,
      int K, const float* __restrict__ bias, int sBias, int act)
{
    constexpr int WM = BMT / 2;
    constexpr int STGB = (BMT + BN) * PROW * 2;
    constexpr int BOFFB = BMT * PROW * 2;
    extern __shared__ __align__(16) char smem[];
    const int tid = threadIdx.x, wid = tid >> 5, lane = tid & 31;
    const int m0 = blockIdx.y * BMT, n0 = blockIdx.x * BN, lvl = blockIdx.z;
    const int lda = 2 * K;
    A += (long)lvl * sA + (long)m0 * lda;
    B += (long)lvl * sB + (long)n0 * lda;
    C += (long)lvl * sC;
    const float* bp = bias ? bias + (long)lvl * sBias + n0 : nullptr;

    const int wm = (wid >> 2) * WM, wn = (wid & 3) * 32;
    const uint32_t sb = (uint32_t)__cvta_generic_to_shared(smem);

    float acc[WM / 16][4][4] = {};
    const int ntp = K / BK, nt = 3 * ntp;
    const int rrow = tid >> 3, rch = tid & 7;

    auto load_tile = [&](int g, int s) {
        int p = (g >= 2 * ntp) ? 2 : (g >= ntp ? 1 : 0);
        int j = g - p * ntp;
        int ao = ((p == 2) ? K : 0) + j * BK;
        int bo = ((p == 1) ? K : 0) + j * BK;
        const __nv_bfloat16* Ag = A + ao;
        const __nv_bfloat16* Bg = B + bo;
        uint32_t base = sb + (uint32_t)s * STGB;
#pragma unroll
        for (int it = 0; it < BMT / 32; it++) {
            int r = rrow + it * 32;
            uint32_t o = (uint32_t)(r * PROW + rch * 8) * 2;
            cp16(base + o, Ag + (long)r * lda + rch * 8);
        }
#pragma unroll
        for (int it = 0; it < 4; it++) {
            int r = rrow + it * 32;
            uint32_t o = (uint32_t)(r * PROW + rch * 8) * 2;
            cp16(base + BOFFB + o, Bg + (long)r * lda + rch * 8);
        }
    };

    load_tile(0, 0); cp_commit();
    load_tile(1, 1); cp_commit();

    int st = 0;
    for (int kt = 0; kt < nt; kt++) {
        cp_wait<1>();
        __syncthreads();
        if (kt + 2 < nt) {
            int s2 = st + 2; if (s2 >= 3) s2 -= 3;
            load_tile(kt + 2, s2); cp_commit();
        }
        uint32_t as = sb + (uint32_t)st * STGB;
        uint32_t bs = as + BOFFB;
#pragma unroll
        for (int ks = 0; ks < 4; ks++) {
            int k0 = ks * 16;
            uint32_t b[4][2];
#pragma unroll
            for (int nb2 = 0; nb2 < 2; nb2++) {
                int n  = wn + nb2 * 16 + (lane & 7) + ((lane & 16) ? 8 : 0);
                int kk = k0 + ((lane & 8) ? 8 : 0);
                uint32_t r0, r1, r2, r3;
                ldsm4(r0, r1, r2, r3, bs + (uint32_t)(n * PROW + kk) * 2);
                b[nb2 * 2][0] = r0; b[nb2 * 2][1] = r1;
                b[nb2 * 2 + 1][0] = r2; b[nb2 * 2 + 1][1] = r3;
            }
#pragma unroll
            for (int mi = 0; mi < WM / 16; mi++) {
                int r  = wm + mi * 16 + (lane & 7) + ((lane & 8) ? 8 : 0);
                int kk = k0 + ((lane & 16) ? 8 : 0);
                uint32_t a[4];
                ldsm4(a[0], a[1], a[2], a[3], as + (uint32_t)(r * PROW + kk) * 2);
#pragma unroll
                for (int ni = 0; ni < 4; ni++)
                    mma16816(acc[mi][ni], a, b[ni]);
            }
        }
        if (++st == 3) st = 0;
    }

    const int tr = lane >> 2, tc = (lane & 3) * 2;
#pragma unroll
    for (int mi = 0; mi < WM / 16; mi++) {
        int r = m0 + wm + mi * 16 + tr;
#pragma unroll
        for (int ni = 0; ni < 4; ni++) {
            int c  = wn + ni * 8 + tc;
            float b0 = bp ? bp[c] : 0.f, b1 = bp ? bp[c + 1] : 0.f;
            float v0 = acc[mi][ni][0] + b0, v1 = acc[mi][ni][1] + b1;
            float v2 = acc[mi][ni][2] + b0, v3 = acc[mi][ni][3] + b1;
            if (act) { v0 = fmaxf(v0, 0.f); v1 = fmaxf(v1, 0.f);
                       v2 = fmaxf(v2, 0.f); v3 = fmaxf(v3, 0.f); }
            C[(long)r * ldc + n0 + c]           = v0;
            C[(long)r * ldc + n0 + c + 1]       = v1;
            C[(long)(r + 8) * ldc + n0 + c]     = v2;
            C[(long)(r + 8) * ldc + n0 + c + 1] = v3;
        }
    }
}

// ================= conversions ([hi|lo], 2K rows) =================
__global__ void split2v_k(const float* __restrict__ src, __nv_bfloat16* __restrict__ dst,
                          int K, long total8)
{
    long i = (long)blockIdx.x * 256 + threadIdx.x;
    if (i >= total8) return;
    int kc = K >> 3;
    long r = i / kc; int k = (int)(i - r * kc) * 8;
    const float* s = src + r * (long)K + k;
    float4 v0 = *(const float4*)s;
    float4 v1 = *(const float4*)(s + 4);
    float vv[8] = {v0.x, v0.y, v0.z, v0.w, v1.x, v1.y, v1.z, v1.w};
    union { __nv_bfloat162 h2[4]; uint4 u; } H, L;
#pragma unroll
    for (int j = 0; j < 4; j++) {
        float a = vv[2 * j], b = vv[2 * j + 1];
        __nv_bfloat16 ah = __float2bfloat16(a), bh = __float2bfloat16(b);
        __nv_bfloat16 al = __float2bfloat16(a - __bfloat162float(ah));
        __nv_bfloat16 bl = __float2bfloat16(b - __bfloat162float(bh));
        H.h2[j] = __nv_bfloat162(ah, bh);
        L.h2[j] = __nv_bfloat162(al, bl);
    }
    __nv_bfloat16* d = dst + r * (2L * K) + k;
    *(uint4*)d = H.u;
    *(uint4*)(d + K) = L.u;
}

// scalar split for strided/padded rows (Wih / mem_in)
__global__ void split2_k(const float* __restrict__ src, int lds,
                         __nv_bfloat16* __restrict__ dst, int K, int Kp, long total)
{
    long i = (long)blockIdx.x * 256 + threadIdx.x;
    if (i >= total) return;
    long r = i / Kp; int k = (int)(i - r * Kp);
    float v = (k < K) ? src[r * (long)lds + k] : 0.f;
    __nv_bfloat16 hi = __float2bfloat16(v);
    __nv_bfloat16 lo = __float2bfloat16(v - __bfloat162float(hi));
    __nv_bfloat16* d = dst + r * (2L * Kp);
    d[k] = hi; d[Kp + k] = lo;
}

__global__ void convW1_k(const float* __restrict__ ea, const float* __restrict__ eg)
{
    long i = (long)blockIdx.x * 256 + threadIdx.x;
    if (i >= 4L * 256 * 1024) return;
    int k = (int)(i & 1023); long t = i >> 10; int n = (int)(t & 255); int l = (int)(t >> 8);
    const float* src = ((n < 128) ? ea : eg) + (long)l * (IND + HID) * MLPD;
    float v = src[(long)(IND + k) * MLPD + (n & 127)];
    __nv_bfloat16 hi = __float2bfloat16(v);
    __nv_bfloat16 lo = __float2bfloat16(v - __bfloat162float(hi));
    __nv_bfloat16* d = g_W1b2 + ((long)l * 256 + n) * 2048;
    d[k] = hi; d[1024 + k] = lo;
}

__global__ void convW2_k(const float* __restrict__ W2a, const float* __restrict__ W2g)
{
    long i = (long)blockIdx.x * 256 + threadIdx.x;
    if (i >= 4L * 512 * 256) return;
    int k = (int)(i & 255); long t = i >> 8; int n = (int)(t & 511); int l = (int)(t >> 9);
    float v = (k < 128) ? W2a[(long)l * MLPD * OUTD + (long)k * OUTD + n]
                        : -W2g[(long)l * MLPD * OUTD + (long)(k - 128) * OUTD + n];
    __nv_bfloat16 hi = __float2bfloat16(v);
    __nv_bfloat16 lo = __float2bfloat16(v - __bfloat162float(hi));
    __nv_bfloat16* d = g_W2b2 + ((long)l * 512 + n) * 512;
    d[k] = hi; d[256 + k] = lo;
}

__global__ void b2diff_k(const float* __restrict__ a, const float* __restrict__ g)
{
    int i = blockIdx.x * 256 + threadIdx.x;
    g_b2d[i] = a[i] - g[i];
}

// ================= tail kernels =================
__global__ void xa_part(const float* __restrict__ x,
                        const float* __restrict__ eaW1, const float* __restrict__ egW1)
{
    int ks = blockIdx.x, l = blockIdx.y, which = blockIdx.z, t = threadIdx.x;
    const float* W = (which ? egW1 : eaW1) + (size_t)l * (IND + HID) * MLPD
                     + (size_t)ks * 128 * MLPD;
    const float* xs = x + ks * 128;
    float s = 0.f;
    for (int i = 0; i < 128; i++) s = fmaf(xs[i], W[(size_t)i * MLPD + t], s);
    g_xap[((which * NLV + l) * 4 + ks) * 128 + t] = s;
}
__global__ void xa_red(const float* __restrict__ eab1, const float* __restrict__ egb1)
{
    int l = blockIdx.x, which = blockIdx.y, t = threadIdx.x;
    const float* b = (which ? egb1 : eab1) + l * MLPD;
    float s = b[t];
    for (int ks = 0; ks < 4; ks++) s += g_xap[((which * NLV + l) * 4 + ks) * 128 + t];
    g_xa2[l * 256 + which * 128 + t] = s;
}

__global__ void tension_kernel()
{
    int c = blockIdx.x, t = threadIdx.x;
    const float* row = g_out + (size_t)c * MEMK;
    float s = 0.f;
#pragma unroll
    for (int q = 0; q < 4; q++) { float v = row[t + 128 * q]; s = fmaf(v, v, s); }
    __shared__ float sm[128];
    sm[t] = s; __syncthreads();
    for (int o = 64; o > 0; o >>= 1) { if (t < o) sm[t] += sm[t + o]; __syncthreads(); }
    if (t == 0) g_out[(size_t)c * MEMK + OUTD] = sm[0] * (1.f / OUTD);
}

__global__ void gate_kernel(const float* __restrict__ hid)
{
    int i4 = blockIdx.x * 256 + threadIdx.x;
    int c = i4 >> 8, j4 = (i4 & 255) * 4;
    size_t base = (size_t)c * G3 + j4;
    float4 ir = *(const float4*)(g_gi + base);
    float4 iz = *(const float4*)(g_gi + base + HID);
    float4 in = *(const float4*)(g_gi + base + 2 * HID);
    float4 hr = *(const float4*)(g_gh + base);
    float4 hz = *(const float4*)(g_gh + base + HID);
    float4 hn = *(const float4*)(g_gh + base + 2 * HID);
    float4 hv = *(const float4*)(hid + (size_t)c * HID + j4);
    float4 o;
    {
        float r = 1.f / (1.f + expf(-(ir.x + hr.x)));
        float z = 1.f / (1.f + expf(-(iz.x + hz.x)));
        o.x = (1.f - z) * tanhf(in.x + r * hn.x) + z * hv.x;
        r = 1.f / (1.f + expf(-(ir.y + hr.y)));
        z = 1.f / (1.f + expf(-(iz.y + hz.y)));
        o.y = (1.f - z) * tanhf(in.y + r * hn.y) + z * hv.y;
        r = 1.f / (1.f + expf(-(ir.z + hr.z)));
        z = 1.f / (1.f + expf(-(iz.z + hz.z)));
        o.z = (1.f - z) * tanhf(in.z + r * hn.z) + z * hv.z;
        r = 1.f / (1.f + expf(-(ir.w + hr.w)));
        z = 1.f / (1.f + expf(-(iz.w + hz.w)));
        o.w = (1.f - z) * tanhf(in.w + r * hn.w) + z * hv.w;
    }
    *(float4*)(g_newh + (size_t)c * HID + j4) = o;
}

__global__ void colsum_part()
{
    int jb = blockIdx.x, l = blockIdx.y, cs = blockIdx.z, t = threadIdx.x;
    int j = jb * 128 + t;
    const float* p = g_newh + ((size_t)(l * CPL + cs * 128)) * HID + j;
    float s = 0.f;
    for (int c = 0; c < 128; c++) s += p[(size_t)c * HID];
    g_cs[(l * 8 + cs) * HID + j] = s;
}
__global__ void colsum_red()
{
    int jb = blockIdx.x, l = blockIdx.y, t = threadIdx.x;
    int j = jb * 128 + t;
    float s = 0.f;
    for (int cs = 0; cs < 8; cs++) s += g_cs[(l * 8 + cs) * HID + j];
    g_lm[l * HID + j] = s * (1.f / CPL);
}

template<int SRC>
__global__ void pred_part(const float* __restrict__ W)
{
    int ks = blockIdx.x, l = blockIdx.y, t = threadIdx.x;
    const float* v = (SRC == 0 ? g_lm + (l + 1) * HID : g_pz + l * HID) + ks * 64;
    const float* Wp = W + (size_t)l * HID * HID + (size_t)ks * 64 * HID;
    float acc[4] = {0.f, 0.f, 0.f, 0.f};
    for (int i = 0; i < 64; i++) {
        float a = v[i];
#pragma unroll
        for (int q = 0; q < 4; q++) acc[q] = fmaf(a, Wp[(size_t)i * HID + t + 256 * q], acc[q]);
    }
    float* dst = (SRC == 0 ? g_pp : g_pp2) + (l * 16 + ks) * HID;
#pragma unroll
    for (int q = 0; q < 4; q++) dst[t + 256 * q] = acc[q];
}
template<int SRC>
__global__ void pred_red(const float* __restrict__ b)
{
    int l = blockIdx.x, t = threadIdx.x;
    const float* part = (SRC == 0 ? g_pp : g_pp2) + l * 16 * HID;
#pragma unroll
    for (int q = 0; q < 4; q++) {
        int n = t + 256 * q;
        float s = b[l * HID + n];
        for (int ks = 0; ks < 16; ks++) s += part[ks * HID + n];
        if (SRC == 0) g_pz[l * HID + n] = fmaxf(s, 0.f);
        else          g_pred[l * HID + n] = s;
    }
}

__global__ void finalize_kernel()
{
    int j = threadIdx.x;
    float lm0 = g_lm[j], lm1 = g_lm[HID + j], lm2 = g_lm[2 * HID + j], lm3 = g_lm[3 * HID + j];
    float pe0 = (g_pred[j] - lm0) * 0.05f;
    float pe1 = (g_pred[HID + j] - lm1) * 0.05f;
    float pe2 = (g_pred[2 * HID + j] - lm2) * 0.05f;
    float d0 = pe0, d1 = pe1 - 0.5f * pe0, d2 = pe2 - 0.5f * pe1, d3 = -0.5f * pe2;
    g_delta[j] = d0; g_delta[HID + j] = d1; g_delta[2 * HID + j] = d2; g_delta[3 * HID + j] = d3;
    float m0 = lm0 + d0, m1 = lm1 + d1, m2 = lm2 + d2, m3 = lm3 + d3;
    g_mdelta[j] = m0; g_mdelta[HID + j] = m1; g_mdelta[2 * HID + j] = m2; g_mdelta[3 * HID + j] = m3;
    g_gop[j] = (m0 + m1 + m2 + m3) * 0.25f;
}

__global__ void hh_kernel(float* __restrict__ out, const int* __restrict__ stepp)
{
    int idx = blockIdx.x * blockDim.x + threadIdx.x;
    int c = idx >> 10, j = idx & 1023;
    int l = c >> 10, cl = c & 1023;
    float d = g_delta[l * HID + j];
    float v = 0.7225f * (g_newh[idx] + d) + 0.2775f * g_mdelta[l * HID + j];
    if (*stepp > 5 && cl < (CPL / 4)) v = 0.85f * v + 0.15f * g_gop[j];
    out[513 + idx] = v;
}

__global__ void combined_part(const float* __restrict__ W)
{
    int ks = blockIdx.x, nb = blockIdx.y, t = threadIdx.x;
    int n = nb * 256 + t;
    const float* Wp = W + (size_t)ks * 256 * OUTD;
    const float* lm = g_lm + ks * 256;
    float s = 0.f;
    for (int i = 0; i < 256; i++) s = fmaf(lm[i], Wp[(size_t)i * OUTD + n], s);
    g_cp[ks * OUTD + n] = s;
}
__global__ void combined_red(const float* __restrict__ b, float* __restrict__ out)
{
    int n = blockIdx.x * 256 + threadIdx.x;
    float s = b[n];
    for (int ks = 0; ks < 16; ks++) s += g_cp[ks * OUTD + n];
    out[n] = s;
}

__global__ void avgten_kernel(float* __restrict__ out)
{
    __shared__ float sm[1024];
    int t = threadIdx.x;
    float s = 0.f;
#pragma unroll
    for (int q = 0; q < 4; q++) s += g_out[(size_t)(t + 1024 * q) * MEMK + OUTD];
    sm[t] = s; __syncthreads();
    for (int o = 512; o > 0; o >>= 1) { if (t < o) sm[t] += sm[t + o]; __syncthreads(); }
    if (t == 0) out[OUTD] = sm[0] * (1.f / NC);
}

// ================= host =================
template<class T> static T* sym(const T& s)
{
    void* p = nullptr;
    cudaGetSymbolAddress(&p, s);
    return (T*)p;
}

extern "C" void kernel_launch(void* const* d_in, const int* in_sizes, int n_in,
                              void* d_out, int out_size)
{
    const float* x     = (const float*)d_in[0];
    const float* hid   = (const float*)d_in[1];
    const float* eaW1  = (const float*)d_in[2];
    const float* eab1  = (const float*)d_in[3];
    const float* eaW2  = (const float*)d_in[4];
    const float* eab2  = (const float*)d_in[5];
    const float* egW1  = (const float*)d_in[6];
    const float* egb1  = (const float*)d_in[7];
    const float* egW2  = (const float*)d_in[8];
    const float* egb2  = (const float*)d_in[9];
    const float* Wih   = (const float*)d_in[10];
    const float* Whh   = (const float*)d_in[11];
    const float* bih   = (const float*)d_in[12];
    const float* bhh   = (const float*)d_in[13];
    const float* pW1   = (const float*)d_in[14];
    const float* pb1   = (const float*)d_in[15];
    const float* pW2   = (const float*)d_in[16];
    const float* pb2   = (const float*)d_in[17];
    const float* peiW  = (const float*)d_in[18];
    const float* peib  = (const float*)d_in[19];
    const int*   stepp = (const int*)d_in[20];
    float* out = (float*)d_out;

    const int SM128 = 3 * (128 + BN) * PROW * 2;   // 110592
    const int SM64  = 3 * (64 + BN) * PROW * 2;    // 82944
    cudaFuncSetAttribute(tgemm<128>, cudaFuncAttributeMaxDynamicSharedMemorySize, SM128);
    cudaFuncSetAttribute(tgemm<64>,  cudaFuncAttributeMaxDynamicSharedMemorySize, SM64);

    float* zab  = sym(g_zab[0]);
    float* outb = sym(g_out[0]);
    float* gi   = sym(g_gi[0]);
    float* gh   = sym(g_gh[0]);
    float* xa2  = sym(g_xa2[0]);
    float* b2d  = sym(g_b2d[0]);
    __nv_bfloat16* A2h  = sym(g_A2h[0]);
    __nv_bfloat16* A2m  = sym(g_A2m[0]);
    __nv_bfloat16* zab2 = sym(g_zab2[0]);
    __nv_bfloat16* W2hh = sym(g_W2hh[0]);
    __nv_bfloat16* W2ih = sym(g_W2ih[0]);
    __nv_bfloat16* W1b2 = sym(g_W1b2[0]);
    __nv_bfloat16* W2b2 = sym(g_W2b2[0]);

    auto nb = [](long total) { return (unsigned)((total + 255) / 256); };

    // ---- conversions ----
    xa_part<<<dim3(4, NLV, 2), 128>>>(x, eaW1, egW1);
    xa_red<<<dim3(NLV, 2), 128>>>(eab1, egb1);
    convW1_k<<<nb(4L * 256 * 1024), 256>>>(eaW1, egW1);
    convW2_k<<<nb(4L * 512 * 256), 256>>>(eaW2, egW2);
    b2diff_k<<<8, 256>>>(eab2, egb2);
    split2v_k<<<nb((long)NC * 1024 / 8), 256>>>(hid, A2h, 1024, (long)NC * 1024 / 8);
    split2v_k<<<nb((long)NLV * G3 * 1024 / 8), 256>>>(Whh, W2hh, 1024,
                                                      (long)NLV * G3 * 1024 / 8);
    split2_k<<<nb((long)NLV * G3 * KP_M), 256>>>(Wih, MEMK, W2ih, MEMK, KP_M,
                                                 (long)NLV * G3 * KP_M);

    // ---- MLP1: [za|zg] = relu(h @ [W1a;W1g]^T + xa2) ----
    tgemm<64><<<dim3(256 / BN, CPL / 64, NLV), 256, SM64>>>(
        A2h, (long)CPL * 2048, W1b2, 256L * 2048,
        zab, 256, (long)CPL * 256, 1024, xa2, 256, 1);

    // ---- MLP2: out = [za|zg] @ [W2a;-W2g]^T + (b2a-b2g) ----
    split2v_k<<<nb((long)NC * 256 / 8), 256>>>(zab, zab2, 256, (long)NC * 256 / 8);
    tgemm<64><<<dim3(OUTD / BN, CPL / 64, NLV), 256, SM64>>>(
        zab2, (long)CPL * 512, W2b2, (long)OUTD * 512,
        outb, MEMK, (long)CPL * MEMK, 256, b2d, OUTD, 0);

    // ---- tension + mem_in split ----
    tension_kernel<<<NC, 128>>>();
    split2_k<<<nb((long)NC * KP_M), 256>>>(outb, MEMK, A2m, MEMK, KP_M, (long)NC * KP_M);

    // ---- GRU gi / gh ----
    tgemm<128><<<dim3(G3 / BN, CPL / 128, NLV), 256, SM128>>>(
        A2m, (long)CPL * 2 * KP_M, W2ih, (long)G3 * 2 * KP_M,
        gi, G3, (long)CPL * G3, KP_M, bih, G3, 0);
    tgemm<128><<<dim3(G3 / BN, CPL / 128, NLV), 256, SM128>>>(
        A2h, (long)CPL * 2048, W2hh, (long)G3 * 2048,
        gh, G3, (long)CPL * G3, 1024, bhh, G3, 0);

    // ---- gates + epilogue chain ----
    gate_kernel<<<(NC * HID / 4) / 256, 256>>>(hid);
    colsum_part<<<dim3(8, NLV, 8), 128>>>();
    colsum_red<<<dim3(8, NLV), 128>>>();
    pred_part<0><<<dim3(16, 3), 256>>>(pW1);
    pred_red<0><<<3, 256>>>(pb1);
    pred_part<1><<<dim3(16, 3), 256>>>(pW2);
    pred_red<1><<<3, 256>>>(pb2);
    finalize_kernel<<<1, 1024>>>();
    hh_kernel<<<(NC * HID) / 256, 256>>>(out, stepp);
    combined_part<<<dim3(16, 2), 256>>>(peiW);
    combined_red<<<2, 256>>>(peib, out);
    avgten_kernel<<<1, 1024>>>(out);
}